// round 17
// baseline (speedup 1.0000x reference)
#include <cuda_runtime.h>
#include <cuda_fp16.h>
#include <cstdint>
#include <mma.h>
using namespace nvcuda;

#define DIMC   1024
#define HEADS  16
#define HD     64
#define BATCH  512
#define SEQ    65
#define MROWS  (BATCH * SEQ)   // 33280 = 260*128

// Scratch (allocation-free rule: __device__ globals)
__device__ __half g_qkvh[(size_t)MROWS * 3 * DIMC];   // GEMM1 out (half)
__device__ __half g_xh[(size_t)MROWS * DIMC];         // x -> half
__device__ __half g_wqkvh[(size_t)3 * DIMC * DIMC];   // w_qkv -> half
__device__ __half g_oh[(size_t)MROWS * DIMC];         // attn out hi
__device__ __half g_ol[(size_t)MROWS * DIMC];         // attn out lo
__device__ __half g_wph[(size_t)DIMC * DIMC];         // w_proj hi
__device__ __half g_wpl[(size_t)DIMC * DIMC];         // w_proj lo

// ---------------------------------------------------------------------------
// converts
// ---------------------------------------------------------------------------
__global__ void __launch_bounds__(256) f2h_k(const float4* __restrict__ in,
                                             __half2* __restrict__ out, int n4) {
    int i = blockIdx.x * blockDim.x + threadIdx.x;
    if (i < n4) {
        float4 v = in[i];
        out[2 * i]     = __floats2half2_rn(v.x, v.y);
        out[2 * i + 1] = __floats2half2_rn(v.z, v.w);
    }
}

// split: hi = fp16(x), lo = fp16(x - hi)
__global__ void __launch_bounds__(256) f2hsplit_k(const float4* __restrict__ in,
                                                  __half2* __restrict__ hi,
                                                  __half2* __restrict__ lo, int n4) {
    int i = blockIdx.x * blockDim.x + threadIdx.x;
    if (i < n4) {
        float4 v = in[i];
        __half2 h0 = __floats2half2_rn(v.x, v.y);
        __half2 h1 = __floats2half2_rn(v.z, v.w);
        float2 f0 = __half22float2(h0), f1 = __half22float2(h1);
        hi[2 * i]     = h0;
        hi[2 * i + 1] = h1;
        lo[2 * i]     = __floats2half2_rn(v.x - f0.x, v.y - f0.y);
        lo[2 * i + 1] = __floats2half2_rn(v.z - f1.x, v.w - f1.y);
    }
}

__device__ __forceinline__ void cp_async16(void* smem, const void* gmem) {
    unsigned s = (unsigned)__cvta_generic_to_shared(smem);
    asm volatile("cp.async.cg.shared.global [%0], [%1], 16;\n" ::"r"(s), "l"(gmem));
}

// ---------------------------------------------------------------------------
// GEMM1: fp16 WMMA, fp32 acc, HALF output. C = A[M,K] * B[N,K]^T.
// CTA 128x128, 8 warps (4Mx2N), warp tile 32x64.
// gemm_sp-style pipeline: 2-stage ring, K=32/stage (64B rows, ld 40).
// Epilogue: 2-pass smem staging -> __half2 stores.
// ---------------------------------------------------------------------------
constexpr int TK1  = 32;             // K halfs per stage
constexpr int LD1  = 40;             // padded leading dim (halfs, 80B rows)
constexpr int STG1 = 256 * LD1;      // halfs/stage: A 128 + B 128 rows
#define SMEM_G1 (2 * STG1 * 2)       // 40960 bytes (also >= 64*132*4 staging)

__global__ void __launch_bounds__(256, 2) gemm_h1(const __half* __restrict__ A,
                                                  const __half* __restrict__ B,
                                                  __half* __restrict__ C,
                                                  int M, int N, int K) {
    extern __shared__ __align__(16) __half smh[];
    const int tid  = threadIdx.x;
    const int warp = tid >> 5;
    const int wm   = warp >> 1, wn = warp & 1;
    const int bm   = blockIdx.y * 128, bn = blockIdx.x * 128;

    wmma::fragment<wmma::accumulator, 16, 16, 16, float> acc[2][4];
#pragma unroll
    for (int i = 0; i < 2; i++)
#pragma unroll
        for (int j = 0; j < 4; j++) wmma::fill_fragment(acc[i][j], 0.0f);

    const int lrow = tid >> 2;          // 0..63
    const int lcol = (tid & 3) << 3;    // 0,8,16,24 halfs (16B chunks)

    auto load_stage = [&](int s, int k0) {
        __half* As = smh + s * STG1;
        __half* Bs = As + 128 * LD1;
#pragma unroll
        for (int t = 0; t < 2; t++) {
            int r = lrow + t * 64;
            cp_async16(&As[r * LD1 + lcol], &A[(size_t)(bm + r) * K + k0 + lcol]);
        }
#pragma unroll
        for (int t = 0; t < 2; t++) {
            int r = lrow + t * 64;
            cp_async16(&Bs[r * LD1 + lcol], &B[(size_t)(bn + r) * K + k0 + lcol]);
        }
        asm volatile("cp.async.commit_group;\n" ::: "memory");
    };

    load_stage(0, 0);

    const int niter = K / TK1;   // 32
    for (int j = 0; j < niter; j++) {
        if (j + 1 < niter) load_stage((j + 1) & 1, (j + 1) * TK1);
        else asm volatile("cp.async.commit_group;\n" ::: "memory");
        asm volatile("cp.async.wait_group 1;\n" ::: "memory");
        __syncthreads();

        const __half* As = smh + (j & 1) * STG1;
        const __half* Bs = As + 128 * LD1;
#pragma unroll
        for (int kk = 0; kk < TK1; kk += 16) {
            wmma::fragment<wmma::matrix_a, 16, 16, 16, __half, wmma::row_major> af[2];
            wmma::fragment<wmma::matrix_b, 16, 16, 16, __half, wmma::col_major> bf[4];
#pragma unroll
            for (int i = 0; i < 2; i++)
                wmma::load_matrix_sync(af[i], &As[(wm * 32 + i * 16) * LD1 + kk], LD1);
#pragma unroll
            for (int jj = 0; jj < 4; jj++)
                wmma::load_matrix_sync(bf[jj], &Bs[(wn * 64 + jj * 16) * LD1 + kk], LD1);
#pragma unroll
            for (int i = 0; i < 2; i++)
#pragma unroll
                for (int jj = 0; jj < 4; jj++)
                    wmma::mma_sync(acc[i][jj], af[i], bf[jj], acc[i][jj]);
        }
        __syncthreads();
    }

    // epilogue: two passes of 64 rows via fp32 smem staging -> half2 gmem
    float* stg = (float*)smh;   // 64*132*4 = 33792 <= 40960
#pragma unroll
    for (int pass = 0; pass < 2; pass++) {
        if ((wm >> 1) == pass) {
#pragma unroll
            for (int i = 0; i < 2; i++)
#pragma unroll
                for (int jj = 0; jj < 4; jj++)
                    wmma::store_matrix_sync(
                        &stg[((wm & 1) * 32 + i * 16) * 132 + wn * 64 + jj * 16],
                        acc[i][jj], 132, wmma::mem_row_major);
        }
        __syncthreads();
        const int rbase = pass * 64;
#pragma unroll
        for (int t = 0; t < 16; t++) {
            int idx = tid + t * 256;       // 0..4095
            int row = idx >> 6;            // 0..63
            int c2  = idx & 63;            // half2 column
            float2 v = *(float2*)&stg[row * 132 + c2 * 2];
            *(__half2*)&C[(size_t)(bm + rbase + row) * N + bn + c2 * 2] =
                __floats2half2_rn(v.x, v.y);
        }
        __syncthreads();
    }
}

// ---------------------------------------------------------------------------
// GEMM2 (split-fp16): C = Ah*Bh^T + Ah*Bl^T + Al*Bh^T, fp32 acc.
// CTA 128x128, 8 warps (4Mx2N), warp tile 32x64. 2-stage ring, K=32/stage.
// ---------------------------------------------------------------------------
constexpr int TKS  = 32;
constexpr int LDSP = 40;
constexpr int STGS = 512 * LDSP;     // halfs per stage
#define SMEM_SP (2 * STGS * 2)       // 81920 bytes

__global__ void __launch_bounds__(256, 2) gemm_sp(const __half* __restrict__ Ah,
                                                  const __half* __restrict__ Al,
                                                  const __half* __restrict__ Bh,
                                                  const __half* __restrict__ Bl,
                                                  float* __restrict__ C,
                                                  int M, int N, int K) {
    extern __shared__ __align__(16) __half sms[];
    const int tid  = threadIdx.x;
    const int warp = tid >> 5;
    const int wm   = warp >> 1, wn = warp & 1;
    const int bm   = blockIdx.y * 128, bn = blockIdx.x * 128;

    wmma::fragment<wmma::accumulator, 16, 16, 16, float> acc[2][4];
#pragma unroll
    for (int i = 0; i < 2; i++)
#pragma unroll
        for (int j = 0; j < 4; j++) wmma::fill_fragment(acc[i][j], 0.0f);

    const int lrow = tid >> 2;          // 0..63
    const int lcol = (tid & 3) << 3;    // 0,8,16,24 halfs

    auto load_stage = [&](int s, int k0) {
        __half* stg = sms + s * STGS;
#pragma unroll
        for (int t = 0; t < 8; t++) {
            int row = lrow + t * 64;            // 0..511
            int g = row >> 7, r = row & 127;
            const __half* src =
                (g == 0) ? &Ah[(size_t)(bm + r) * K + k0 + lcol]
              : (g == 1) ? &Al[(size_t)(bm + r) * K + k0 + lcol]
              : (g == 2) ? &Bh[(size_t)(bn + r) * K + k0 + lcol]
                         : &Bl[(size_t)(bn + r) * K + k0 + lcol];
            cp_async16(&stg[row * LDSP + lcol], src);
        }
        asm volatile("cp.async.commit_group;\n" ::: "memory");
    };

    load_stage(0, 0);

    const int niter = K / TKS;   // 32
    for (int j = 0; j < niter; j++) {
        if (j + 1 < niter) load_stage((j + 1) & 1, (j + 1) * TKS);
        else asm volatile("cp.async.commit_group;\n" ::: "memory");
        asm volatile("cp.async.wait_group 1;\n" ::: "memory");
        __syncthreads();

        const __half* As_h = sms + (j & 1) * STGS;
        const __half* As_l = As_h + 128 * LDSP;
        const __half* Bs_h = As_h + 256 * LDSP;
        const __half* Bs_l = As_h + 384 * LDSP;
#pragma unroll
        for (int kk = 0; kk < TKS; kk += 16) {
            wmma::fragment<wmma::matrix_a, 16, 16, 16, __half, wmma::row_major> afh[2], afl[2];
#pragma unroll
            for (int i = 0; i < 2; i++) {
                wmma::load_matrix_sync(afh[i], &As_h[(wm * 32 + i * 16) * LDSP + kk], LDSP);
                wmma::load_matrix_sync(afl[i], &As_l[(wm * 32 + i * 16) * LDSP + kk], LDSP);
            }
#pragma unroll
            for (int jj = 0; jj < 4; jj++) {
                wmma::fragment<wmma::matrix_b, 16, 16, 16, __half, wmma::col_major> bfh, bfl;
                wmma::load_matrix_sync(bfh, &Bs_h[(wn * 64 + jj * 16) * LDSP + kk], LDSP);
                wmma::load_matrix_sync(bfl, &Bs_l[(wn * 64 + jj * 16) * LDSP + kk], LDSP);
#pragma unroll
                for (int i = 0; i < 2; i++) {
                    wmma::mma_sync(acc[i][jj], afh[i], bfh, acc[i][jj]);
                    wmma::mma_sync(acc[i][jj], afh[i], bfl, acc[i][jj]);
                    wmma::mma_sync(acc[i][jj], afl[i], bfh, acc[i][jj]);
                }
            }
        }
        __syncthreads();
    }

#pragma unroll
    for (int i = 0; i < 2; i++)
#pragma unroll
        for (int j = 0; j < 4; j++)
            wmma::store_matrix_sync(
                &C[(size_t)(bm + wm * 32 + i * 16) * N + bn + wn * 64 + j * 16],
                acc[i][j], N, wmma::mem_row_major);
}

// ---------------------------------------------------------------------------
// Fused attention v5: reads HALF qkv. LN in fp32 (from half inputs).
// V is a raw 16B smem copy (already half). Otherwise identical to v4.
// ---------------------------------------------------------------------------
#define LDQH  72
#define LDPH  88
#define LDS2  84
#define ATT_QH 0
#define ATT_KH 11520
#define ATT_VH 23040
#define ATT_PH 34560
#define ATT_S  48640
#define SMEM_ATT3 75520

__global__ void __launch_bounds__(256) attn_kernel(
    const __half* __restrict__ qkv, const float* __restrict__ bias,
    const float* __restrict__ bscale_p,
    const float* __restrict__ qn_w, const float* __restrict__ qn_b,
    const float* __restrict__ kn_w, const float* __restrict__ kn_b,
    __half* __restrict__ outh, __half* __restrict__ outl) {
    extern __shared__ __align__(16) char smc[];
    __half* qh  = (__half*)(smc + ATT_QH);
    __half* kh  = (__half*)(smc + ATT_KH);
    __half* vh  = (__half*)(smc + ATT_VH);
    __half* ph  = (__half*)(smc + ATT_PH);
    float*  s_s = (float*)(smc + ATT_S);

    const int tid = threadIdx.x, lane = tid & 31, warp = tid >> 5;
    const int h = blockIdx.x, b = blockIdx.y;
    const float bscale = *bscale_p;
    const size_t base = (size_t)b * SEQ * 3072 + (size_t)h * 64;

    // zero: full P tile + vh pad rows 65..79
    {
        unsigned* phz = (unsigned*)ph;
        for (int i = tid; i < 3520; i += 256) phz[i] = 0u;
        unsigned* vhz = (unsigned*)vh + 65 * (LDQH / 2);
        for (int i = tid; i < 15 * (LDQH / 2); i += 256) vhz[i] = 0u;
    }

    // ---- LN phase: batch ALL gmem loads first, then reduce (fp32 math) ----
    const float qw0 = qn_w[lane], qw1 = qn_w[lane + 32];
    const float qb0 = qn_b[lane], qb1 = qn_b[lane + 32];
    const float kw0 = kn_w[lane], kw1 = kn_w[lane + 32];
    const float kb0 = kn_b[lane], kb1 = kn_b[lane + 32];

    float xq0[9], xq1[9], xk0[9], xk1[9];
#pragma unroll
    for (int t = 0; t < 9; t++) {
        int n = warp + t * 8;
        if (n < SEQ) {
            const __half* row = qkv + base + (size_t)n * 3072;
            xq0[t] = __half2float(row[lane]);
            xq1[t] = __half2float(row[lane + 32]);
            xk0[t] = __half2float(row[1024 + lane]);
            xk1[t] = __half2float(row[1024 + lane + 32]);
        }
    }
#pragma unroll
    for (int t = 0; t < 9; t++) {
        int n = warp + t * 8;
        if (n < SEQ) {
            float x0 = xq0[t], x1 = xq1[t];
            float s = x0 + x1, sq = x0 * x0 + x1 * x1;
#pragma unroll
            for (int o = 16; o; o >>= 1) {
                s += __shfl_xor_sync(0xffffffffu, s, o);
                sq += __shfl_xor_sync(0xffffffffu, sq, o);
            }
            float mu = s * (1.f / 64.f);
            float rstd = rsqrtf(sq * (1.f / 64.f) - mu * mu + 1e-5f);
            qh[n * LDQH + lane]      = __float2half(((x0 - mu) * rstd * qw0 + qb0) * 0.125f);
            qh[n * LDQH + lane + 32] = __float2half(((x1 - mu) * rstd * qw1 + qb1) * 0.125f);

            x0 = xk0[t]; x1 = xk1[t];
            s = x0 + x1; sq = x0 * x0 + x1 * x1;
#pragma unroll
            for (int o = 16; o; o >>= 1) {
                s += __shfl_xor_sync(0xffffffffu, s, o);
                sq += __shfl_xor_sync(0xffffffffu, sq, o);
            }
            mu = s * (1.f / 64.f);
            rstd = rsqrtf(sq * (1.f / 64.f) - mu * mu + 1e-5f);
            kh[n * LDQH + lane]      = __float2half((x0 - mu) * rstd * kw0 + kb0);
            kh[n * LDQH + lane + 32] = __float2half((x1 - mu) * rstd * kw1 + kb1);
        }
    }
    __syncthreads();

    // ---- S = Q K^T (warps 0-4); warps 5-7 copy V (raw 16B chunks) ----
    if (warp < 5) {
        wmma::fragment<wmma::accumulator, 16, 16, 16, float> sacc[5];
#pragma unroll
        for (int m = 0; m < 5; m++) wmma::fill_fragment(sacc[m], 0.0f);
#pragma unroll
        for (int kk = 0; kk < 4; kk++) {
            wmma::fragment<wmma::matrix_a, 16, 16, 16, __half, wmma::row_major> aq;
            wmma::load_matrix_sync(aq, &qh[warp * 16 * LDQH + kk * 16], LDQH);
#pragma unroll
            for (int m = 0; m < 5; m++) {
                wmma::fragment<wmma::matrix_b, 16, 16, 16, __half, wmma::col_major> bk;
                wmma::load_matrix_sync(bk, &kh[m * 16 * LDQH + kk * 16], LDQH);
                wmma::mma_sync(sacc[m], aq, bk, sacc[m]);
            }
        }
#pragma unroll
        for (int m = 0; m < 5; m++)
            wmma::store_matrix_sync(&s_s[warp * 16 * LDS2 + m * 16], sacc[m],
                                    LDS2, wmma::mem_row_major);
    } else {
        // 65 rows x 8 chunks (16B = 8 halfs) = 520 chunks over 96 threads
#pragma unroll
        for (int t = 0; t < 6; t++) {
            int i = (tid - 160) + t * 96;
            if (i < SEQ * 8) {
                int n = i >> 3, c8 = (i & 7) << 3;
                *(uint4*)&vh[n * LDQH + c8] =
                    *(const uint4*)&qkv[base + (size_t)n * 3072 + 2048 + c8];
            }
        }
    }

    // ---- prefetch bias into registers BEFORE the post-MMA barrier ----
    float bp0[9], bp1[9], bp2[9];
#pragma unroll
    for (int t = 0; t < 9; t++) {
        int n = warp + t * 8;
        if (n < SEQ) {
            const float* brow = &bias[((size_t)h * SEQ + n) * SEQ];
            bp0[t] = brow[lane];
            bp1[t] = brow[lane + 32];
            bp2[t] = (lane == 0) ? brow[64] : 0.f;
        }
    }
    __syncthreads();

    // ---- softmax rows (fp32, bias from registers); write P as half ----
#pragma unroll
    for (int t = 0; t < 9; t++) {
        int n = warp + t * 8;
        if (n < SEQ) {
            float v0 = s_s[n * LDS2 + lane]      + bp0[t] * bscale;
            float v1 = s_s[n * LDS2 + lane + 32] + bp1[t] * bscale;
            float v2 = (lane == 0) ? s_s[n * LDS2 + 64] + bp2[t] * bscale : -3.4e38f;
            float mx = fmaxf(fmaxf(v0, v1), v2);
#pragma unroll
            for (int o = 16; o; o >>= 1)
                mx = fmaxf(mx, __shfl_xor_sync(0xffffffffu, mx, o));
            float e0 = __expf(v0 - mx), e1 = __expf(v1 - mx);
            float e2 = (lane == 0) ? __expf(v2 - mx) : 0.f;
            float sum = e0 + e1 + e2;
#pragma unroll
            for (int o = 16; o; o >>= 1) sum += __shfl_xor_sync(0xffffffffu, sum, o);
            float inv = 1.f / sum;
            ph[n * LDPH + lane]      = __float2half(e0 * inv);
            ph[n * LDPH + lane + 32] = __float2half(e1 * inv);
            if (lane == 0) ph[n * LDPH + 64] = __float2half(e2 * inv);
        }
    }
    __syncthreads();

    // ---- O = P V on tensor cores (warps 0-4) ----
    if (warp < 5) {
        wmma::fragment<wmma::accumulator, 16, 16, 16, float> oacc[4];
#pragma unroll
        for (int j = 0; j < 4; j++) wmma::fill_fragment(oacc[j], 0.0f);
#pragma unroll
        for (int kk = 0; kk < 5; kk++) {
            wmma::fragment<wmma::matrix_a, 16, 16, 16, __half, wmma::row_major> ap;
            wmma::load_matrix_sync(ap, &ph[warp * 16 * LDPH + kk * 16], LDPH);
#pragma unroll
            for (int j = 0; j < 4; j++) {
                wmma::fragment<wmma::matrix_b, 16, 16, 16, __half, wmma::row_major> bv;
                wmma::load_matrix_sync(bv, &vh[kk * 16 * LDQH + j * 16], LDQH);
                wmma::mma_sync(oacc[j], ap, bv, oacc[j]);
            }
        }
#pragma unroll
        for (int j = 0; j < 4; j++)
            wmma::store_matrix_sync(&s_s[warp * 16 * LDS2 + j * 16], oacc[j],
                                    LDS2, wmma::mem_row_major);
    }
    __syncthreads();

    // ---- epilogue: split-fp16 write (hi, lo) -> feeds split GEMM2 ----
    for (int i = tid; i < SEQ * 64; i += 256) {
        int n = i >> 6, d = i & 63;
        float v = s_s[n * LDS2 + d];
        __half hh = __float2half_rn(v);
        __half ll = __float2half_rn(v - __half2float(hh));
        size_t o = ((size_t)b * SEQ + n) * DIMC + (size_t)h * 64 + d;
        outh[o] = hh;
        outl[o] = ll;
    }
}

// ---------------------------------------------------------------------------
extern "C" void kernel_launch(void* const* d_in, const int* in_sizes, int n_in,
                              void* d_out, int out_size) {
    const float* x      = (const float*)d_in[0];
    const float* w_qkv  = (const float*)d_in[1];
    const float* w_proj = (const float*)d_in[2];
    const float* qn_w   = (const float*)d_in[3];
    const float* qn_b   = (const float*)d_in[4];
    const float* kn_w   = (const float*)d_in[5];
    const float* kn_b   = (const float*)d_in[6];
    const float* bias   = (const float*)d_in[7];
    const float* bscale = (const float*)d_in[8];
    float* out          = (float*)d_out;

    __half *qkvh_p, *xh_p, *wqkvh_p, *oh_p, *ol_p, *wph_p, *wpl_p;
    cudaGetSymbolAddress((void**)&qkvh_p, g_qkvh);
    cudaGetSymbolAddress((void**)&xh_p, g_xh);
    cudaGetSymbolAddress((void**)&wqkvh_p, g_wqkvh);
    cudaGetSymbolAddress((void**)&oh_p, g_oh);
    cudaGetSymbolAddress((void**)&ol_p, g_ol);
    cudaGetSymbolAddress((void**)&wph_p, g_wph);
    cudaGetSymbolAddress((void**)&wpl_p, g_wpl);

    cudaFuncSetAttribute(gemm_h1, cudaFuncAttributeMaxDynamicSharedMemorySize,
                         SMEM_G1);
    cudaFuncSetAttribute(gemm_sp, cudaFuncAttributeMaxDynamicSharedMemorySize,
                         SMEM_SP);
    cudaFuncSetAttribute(attn_kernel, cudaFuncAttributeMaxDynamicSharedMemorySize,
                         SMEM_ATT3);

    // 0) operand converts: fp16 for GEMM1; split-fp16 for w_proj
    int n4x = MROWS * DIMC / 4;
    f2h_k<<<(n4x + 255) / 256, 256>>>((const float4*)x, (__half2*)xh_p, n4x);
    int n4wq = 3 * DIMC * DIMC / 4;
    f2h_k<<<(n4wq + 255) / 256, 256>>>((const float4*)w_qkv, (__half2*)wqkvh_p, n4wq);
    int n4wp = DIMC * DIMC / 4;
    f2hsplit_k<<<(n4wp + 255) / 256, 256>>>((const float4*)w_proj,
                                            (__half2*)wph_p, (__half2*)wpl_p, n4wp);

    // 1) QKV projection (fp16 tensor, half out): [33280,1024] x [3072,1024]^T
    gemm_h1<<<dim3(3 * DIMC / 128, MROWS / 128), 256, SMEM_G1>>>(
        xh_p, wqkvh_p, qkvh_p, MROWS, 3 * DIMC, DIMC);
    // 2) Fused LN + attention per (b,h); half in, split-fp16 out
    attn_kernel<<<dim3(HEADS, BATCH), 256, SMEM_ATT3>>>(
        qkvh_p, bias, bscale, qn_w, qn_b, kn_w, kn_b, oh_p, ol_p);
    // 3) Output projection (split-fp16, 3-term): [33280,1024] x [1024,1024]^T
    gemm_sp<<<dim3(DIMC / 128, MROWS / 128), 256, SMEM_SP>>>(
        oh_p, ol_p, wph_p, wpl_p, out, MROWS, DIMC, DIMC);
}